// round 5
// baseline (speedup 1.0000x reference)
#include <cuda_runtime.h>
#include <cstdint>

// 3x3 stride-1 pad-1 conv, 1 channel, weight = w * outer(kx,kx), kx=[den,1,den].
// x: (16,1,2048,2048) fp32 -> out same shape.
// cp.async tile loads, div-free indexing, 2-group pipeline: compute top half
// of the tile while the bottom half is still in flight.

#define TCOLS 128
#define TROWS 32
#define SROWS 34            // TROWS + 2
#define PITCH 136           // 4 (align) + 128 + 4

__global__ __launch_bounds__(256)
void conv3x3_pipe(const float* __restrict__ x,
                  const float* __restrict__ w,
                  const float* __restrict__ den,
                  float* __restrict__ out,
                  int H, int W)
{
    __shared__ float tile[SROWS * PITCH];

    const int tid  = threadIdx.x;
    const int lane = tid & 31;
    const int wid  = tid >> 5;

    const int colbase = blockIdx.x * TCOLS;
    const int row0    = blockIdx.y * TROWS;
    const int b       = blockIdx.z;

    const size_t img = (size_t)H * W;
    const float* __restrict__ xb = x + (size_t)b * img;
    float*       __restrict__ ob = out + (size_t)b * img;

    const uint32_t sbase = (uint32_t)__cvta_generic_to_shared(tile);

    // interior chunk c2 = r*32 + c  ->  smem [r*PITCH + 4 + 4c], gmem (row0-1+r, colbase+4c)
    auto issue_interior = [&](int c2) {
        const int r  = c2 >> 5;
        const int c  = c2 & 31;
        const int gy = row0 - 1 + r;
        const bool valid = (unsigned)gy < (unsigned)H;
        const float* src = xb + (valid ? ((size_t)gy * W + colbase + 4 * c) : 0);
        const int ss = valid ? 16 : 0;
        const uint32_t dst = sbase + (uint32_t)(r * PITCH + 4 + 4 * c) * 4u;
        asm volatile("cp.async.cg.shared.global [%0], [%1], 16, %2;"
                     :: "r"(dst), "l"(src), "r"(ss));
    };
    // single-float halo columns: smem idx 3 (left, gx=colbase-1) / 132 (right, gx=colbase+128)
    auto issue_edge = [&](int r, bool left) {
        const int gy = row0 - 1 + r;
        const int gx = left ? (colbase - 1) : (colbase + TCOLS);
        const bool valid = ((unsigned)gy < (unsigned)H) & ((unsigned)gx < (unsigned)W);
        const float* src = xb + (valid ? ((size_t)gy * W + gx) : 0);
        const int ss = valid ? 4 : 0;
        const uint32_t dst = sbase + (uint32_t)(r * PITCH + (left ? 3 : 132)) * 4u;
        asm volatile("cp.async.ca.shared.global [%0], [%1], 4, %2;"
                     :: "r"(dst), "l"(src), "r"(ss));
    };

    // ---- group A: smem rows [0,18) = 576 interior chunks + 36 edges ----
    issue_interior(tid);
    issue_interior(tid + 256);
    if (tid < 64) issue_interior(tid + 512);
    if (tid >= 128 && tid < 146) issue_edge(tid - 128, true);
    if (tid >= 192 && tid < 210) issue_edge(tid - 192, false);
    asm volatile("cp.async.commit_group;");

    // ---- group B: smem rows [18,34) = 512 interior chunks + 32 edges ----
    issue_interior(tid + 576);
    issue_interior(tid + 832);
    if (tid < 16)               issue_edge(18 + tid, true);
    if (tid >= 32 && tid < 48)  issue_edge(18 + tid - 32, false);
    asm volatile("cp.async.commit_group;");

    // effective 3x3 weights (overlaps with loads)
    const float d = den[0];
    const float kv[3] = {d, 1.0f, d};
    float k[9];
    #pragma unroll
    for (int i = 0; i < 3; i++)
        #pragma unroll
        for (int j = 0; j < 3; j++)
            k[i * 3 + j] = __ldg(&w[i * 3 + j]) * kv[i] * kv[j];

    // lane window: smem floats [3+4*lane .. 8+4*lane] of a row
    const int base_f = 4 * lane;
    auto ldrow = [&](int r, float* s) {
        const float* p = &tile[r * PITCH + base_f];
        const float4 v = *reinterpret_cast<const float4*>(p + 4);
        s[0] = p[3]; s[1] = v.x; s[2] = v.y; s[3] = v.z; s[4] = v.w; s[5] = p[8];
    };
    // compute 2 output rows starting at local row lr (smem rows lr..lr+3)
    auto do2rows = [&](int lr) {
        float s0[6], s1[6], s2[6];
        ldrow(lr,     s0);
        ldrow(lr + 1, s1);
        float* ro = ob + (size_t)(row0 + lr) * W + colbase + base_f;
        #pragma unroll
        for (int oo = 0; oo < 2; oo++) {
            ldrow(lr + 2 + oo, s2);
            float a0 = 0.f, a1 = 0.f, a2 = 0.f, a3 = 0.f;
            #pragma unroll
            for (int i = 0; i < 3; i++) {
                const float* s = (i == 0) ? s0 : (i == 1) ? s1 : s2;
                const float w0 = k[3 * i], w1 = k[3 * i + 1], w2 = k[3 * i + 2];
                a0 = fmaf(w0, s[0], fmaf(w1, s[1], fmaf(w2, s[2], a0)));
                a1 = fmaf(w0, s[1], fmaf(w1, s[2], fmaf(w2, s[3], a1)));
                a2 = fmaf(w0, s[2], fmaf(w1, s[3], fmaf(w2, s[4], a2)));
                a3 = fmaf(w0, s[3], fmaf(w1, s[4], fmaf(w2, s[5], a3)));
            }
            *reinterpret_cast<float4*>(ro) = make_float4(a0, a1, a2, a3);
            ro += W;
            #pragma unroll
            for (int i = 0; i < 6; i++) { s0[i] = s1[i]; s1[i] = s2[i]; }
        }
    };

    // ---- pipeline: top half computes while bottom half streams in ----
    asm volatile("cp.async.wait_group 1;");   // group A complete (this thread)
    __syncthreads();                           // A visible to all warps
    do2rows(2 * wid);                          // output rows [2w, 2w+2): smem rows 2w..2w+3 <= 17

    asm volatile("cp.async.wait_group 0;");   // group B complete
    __syncthreads();                           // B visible
    do2rows(16 + 2 * wid);                     // smem rows 16+2w..19+2w <= 33
}

extern "C" void kernel_launch(void* const* d_in, const int* in_sizes, int n_in,
                              void* d_out, int out_size)
{
    const float* x   = (const float*)d_in[0];   // (16,1,2048,2048) fp32
    const float* w   = (const float*)d_in[1];   // (1,1,3,3) fp32
    const float* den = (const float*)d_in[2];   // (1,) fp32
    float* out = (float*)d_out;

    const int B = 16, H = 2048, W = 2048;
    (void)in_sizes; (void)n_in; (void)out_size;

    dim3 grid(W / TCOLS, H / TROWS, B);   // 16 x 64 x 16 = 16384 CTAs
    dim3 block(256);
    conv3x3_pipe<<<grid, block>>>(x, w, den, out, H, W);
}